// round 13
// baseline (speedup 1.0000x reference)
#include <cuda_runtime.h>
#include <cuda_bf16.h>
#include <math.h>

#define B_ 8
#define N_ 2048
#define D_ 256
#define F_ 128
#define R_ 2
#define KQ 384            // D_+F_
#define M_TOT (B_*N_)     // 16384

typedef __nv_bfloat16 bf16;
typedef __nv_bfloat162 bf162;

// ---------------- scratch ----------------
__device__ float g_x1[B_*F_];
__device__ bf16  g_q16[(size_t)M_TOT*D_];
__device__ bf16  g_k16[(size_t)B_*R_*N_*D_];
__device__ bf16  g_v16[(size_t)B_*R_*N_*D_];
__device__ bf16  g_h16[(size_t)M_TOT*R_*D_];
__device__ bf16  g_wq16[KQ*D_];
__device__ bf16  g_wk16[R_*KQ*D_];
__device__ bf16  g_wv16[R_*KQ*D_];
__device__ bf16  g_wf16[R_*D_*D_];

// ---------------- PTX helpers ----------------
__device__ __forceinline__ unsigned smem_u32(const void* p) {
    return (unsigned)__cvta_generic_to_shared(p);
}
#define LDSM_X4(r0,r1,r2,r3,addr) \
    asm volatile("ldmatrix.sync.aligned.m8n8.x4.shared.b16 {%0,%1,%2,%3}, [%4];" \
        : "=r"(r0),"=r"(r1),"=r"(r2),"=r"(r3) : "r"(addr))
#define LDSM_X4T(r0,r1,r2,r3,addr) \
    asm volatile("ldmatrix.sync.aligned.m8n8.x4.trans.shared.b16 {%0,%1,%2,%3}, [%4];" \
        : "=r"(r0),"=r"(r1),"=r"(r2),"=r"(r3) : "r"(addr))
#define LDSM_X2T(r0,r1,addr) \
    asm volatile("ldmatrix.sync.aligned.m8n8.x2.trans.shared.b16 {%0,%1}, [%2];" \
        : "=r"(r0),"=r"(r1) : "r"(addr))
#define MMA16816(c,a0,a1,a2,a3,b0,b1) \
    asm volatile("mma.sync.aligned.m16n8k16.row.col.f32.bf16.bf16.f32 " \
        "{%0,%1,%2,%3},{%4,%5,%6,%7},{%8,%9},{%0,%1,%2,%3};" \
        : "+f"(c[0]),"+f"(c[1]),"+f"(c[2]),"+f"(c[3]) \
        : "r"(a0),"r"(a1),"r"(a2),"r"(a3),"r"(b0),"r"(b1))
#define CPA16(s,g) asm volatile("cp.async.cg.shared.global [%0], [%1], 16;" :: "r"(s), "l"(g))
#define CPA_COMMIT() asm volatile("cp.async.commit_group;" ::: "memory")
#define CPA_WAIT1() asm volatile("cp.async.wait_group 1;" ::: "memory")
#define CPA_WAIT0() asm volatile("cp.async.wait_group 0;" ::: "memory")

static __device__ __forceinline__ unsigned pk2(float a, float b) {
    bf162 t = __float22bfloat162_rn(make_float2(a, b));
    return *(unsigned*)&t;
}

// ---------------- x1 ----------------
__global__ void k_x1(const float* __restrict__ input_x,
                     const float* __restrict__ Ww,
                     const float* __restrict__ Wb) {
    __shared__ float row[F_];
    int b = blockIdx.x, j = threadIdx.x;
    row[j] = input_x[b*F_ + j];
    __syncthreads();
    float s = Wb[j];
    #pragma unroll 4
    for (int c = 0; c < F_; c++) s = fmaf(row[c], Ww[c*F_ + j], s);
    g_x1[b*F_ + j] = s;
}

// ---------------- weights to bf16 ----------------
__global__ void k_cvtw(const float* __restrict__ wq, const float* __restrict__ wk,
                       const float* __restrict__ wv, const float* __restrict__ wf) {
    int i = blockIdx.x * blockDim.x + threadIdx.x;
    int e = i * 2;
    const int SQ = KQ*D_, SK = R_*KQ*D_, SF = R_*D_*D_;
    if (e < SQ) {
        *(bf162*)(g_wq16 + e) = __float22bfloat162_rn(*(const float2*)(wq + e));
    } else if (e < SQ + SK) {
        int o = e - SQ;
        *(bf162*)(g_wk16 + o) = __float22bfloat162_rn(*(const float2*)(wk + o));
    } else if (e < SQ + 2*SK) {
        int o = e - SQ - SK;
        *(bf162*)(g_wv16 + o) = __float22bfloat162_rn(*(const float2*)(wv + o));
    } else if (e < SQ + 2*SK + SF) {
        int o = e - SQ - 2*SK;
        *(bf162*)(g_wf16 + o) = __float22bfloat162_rn(*(const float2*)(wf + o));
    }
}

// inline concat loader: 8 bf16 of [node_embed | x1] row m, cols c..c+7
__device__ __forceinline__ uint4 load_cat8(const float* __restrict__ ne, int m, int c) {
    float4 f0, f1;
    if (c < D_) {
        const float* p = ne + (size_t)m*D_ + c;
        f0 = *(const float4*)p; f1 = *(const float4*)(p + 4);
    } else {
        const float* p = g_x1 + (size_t)(m >> 11)*F_ + (c - D_);
        f0 = *(const float4*)p; f1 = *(const float4*)(p + 4);
    }
    uint4 r;
    r.x = pk2(f0.x, f0.y); r.y = pk2(f0.z, f0.w);
    r.z = pk2(f1.x, f1.y); r.w = pk2(f1.z, f1.w);
    return r;
}

// ============ qkv GEMM (proven shape: CTA 128x128, 8 warps 64x32) ============
__global__ void __launch_bounds__(256) k_qkv16(
        const float* __restrict__ node_embed,
        const float* __restrict__ WQ_b, const float* __restrict__ WK_b,
        const float* __restrict__ WV_b) {
    __shared__ bf16 As[128*40];
    __shared__ bf16 Bs[32*136];
    int tid = threadIdx.x;
    int l = tid & 31, warp = tid >> 5;
    int warp_m = warp & 1, warp_n = warp >> 1;
    int quad = l >> 2, qlane = l & 3;

    int bn = blockIdx.x;
    int m0 = blockIdx.y * 128;
    int chunk = bn >> 1;
    int j0 = (bn & 1) * 128;

    const bf16* Wg; const float* bias;
    if (chunk == 0)      { Wg = g_wq16;                           bias = WQ_b; }
    else if (chunk <= 2) { Wg = g_wk16 + (size_t)(chunk-1)*KQ*D_; bias = WK_b + (chunk-1)*D_; }
    else                 { Wg = g_wv16 + (size_t)(chunk-3)*KQ*D_; bias = WV_b + (chunk-3)*D_; }

    float acc[4][4][4];
    #pragma unroll
    for (int i=0;i<4;i++) for (int j=0;j<4;j++) for (int c=0;c<4;c++) acc[i][j][c]=0.f;

    int a_row = tid >> 2, a_seg = tid & 3;
    int b_row = tid >> 4, b_seg = tid & 15;

    int arow = (l & 7) + ((l >> 3) & 1) * 8;
    int acol = (l >> 4) * 8;
    unsigned a_base = smem_u32(As) + (unsigned)(((warp_m*64 + arow)*40 + acol) * 2);
    int lt = l & 15;
    unsigned b_base = smem_u32(Bs) + (unsigned)((lt*136 + warp_n*32) * 2);

    {
        #pragma unroll
        for (int it=0; it<2; it++) {
            int r = a_row + it*64;
            *(uint4*)&As[r*40 + a_seg*8] = load_cat8(node_embed, m0 + r, a_seg*8);
            int rb = b_row + it*16;
            *(uint4*)&Bs[rb*136 + b_seg*8] =
                *(const uint4*)(Wg + (size_t)rb*D_ + j0 + b_seg*8);
        }
    }
    __syncthreads();

    for (int c0 = 0; c0 < KQ; c0 += 32) {
        bool nxt = (c0 + 32 < KQ);
        uint4 pa0,pa1,pb0,pb1;
        if (nxt) {
            pa0 = load_cat8(node_embed, m0 + a_row,      c0+32 + a_seg*8);
            pa1 = load_cat8(node_embed, m0 + a_row + 64, c0+32 + a_seg*8);
            pb0 = *(const uint4*)(Wg + (size_t)(c0+32+b_row   )*D_ + j0 + b_seg*8);
            pb1 = *(const uint4*)(Wg + (size_t)(c0+32+b_row+16)*D_ + j0 + b_seg*8);
        }
        #pragma unroll
        for (int ks = 0; ks < 2; ks++) {
            unsigned a0,a1,a2,a3;
            unsigned bfr[4][2];
            #pragma unroll
            for (int nt=0; nt<4; nt++) {
                unsigned addr = b_base + (unsigned)((ks*16*136 + nt*8) * 2);
                LDSM_X2T(bfr[nt][0], bfr[nt][1], addr);
            }
            #pragma unroll
            for (int mt=0; mt<4; mt++) {
                unsigned addr = a_base + (unsigned)((mt*16*40 + ks*16) * 2);
                LDSM_X4(a0,a1,a2,a3, addr);
                #pragma unroll
                for (int nt=0; nt<4; nt++)
                    MMA16816(acc[mt][nt], a0,a1,a2,a3, bfr[nt][0], bfr[nt][1]);
            }
        }
        __syncthreads();
        if (nxt) {
            *(uint4*)&As[(a_row   )*40 + a_seg*8] = pa0;
            *(uint4*)&As[(a_row+64)*40 + a_seg*8] = pa1;
            *(uint4*)&Bs[(b_row   )*136 + b_seg*8] = pb0;
            *(uint4*)&Bs[(b_row+16)*136 + b_seg*8] = pb1;
            __syncthreads();
        }
    }

    #pragma unroll
    for (int mt=0; mt<4; mt++) {
        #pragma unroll
        for (int half=0; half<2; half++) {
            int i = m0 + warp_m*64 + mt*16 + quad + half*8;
            int bb = i >> 11, ntok = i & (N_-1);
            #pragma unroll
            for (int nt=0; nt<4; nt++) {
                int jj = j0 + warp_n*32 + nt*8 + qlane*2;
                float2 bv = *(const float2*)(bias + jj);
                float v0 = acc[mt][nt][half*2+0] + bv.x;
                float v1 = acc[mt][nt][half*2+1] + bv.y;
                bf16* dst;
                if (chunk == 0)      dst = g_q16 + (size_t)i*D_ + jj;
                else if (chunk <= 2) dst = g_k16 + ((size_t)(bb*R_ + (chunk-1))*N_ + ntok)*D_ + jj;
                else                 dst = g_v16 + ((size_t)(bb*R_ + (chunk-3))*N_ + ntok)*D_ + jj;
                *(bf162*)dst = __float22bfloat162_rn(make_float2(v0, v1));
            }
        }
    }
}

// ============ fused attention, register-resident P (FA2 style) ============
// 128 q-rows/CTA, 512 thr = 16 warps: wm = warp&7 (m16 rows), wd = warp>>3 (d-half).
// Each warp: S m16 x kv64 (full tile; duplicated across the 2 wd twins),
// exp+mask in regs, pack C-frags -> A-frags (pa), PV m16 x d128 with k=64.
// No P smem, no cross-warp rowsum. K/V double-buffered; 2 barriers/tile.
// smem: q 128x512B | K 2x 64x512B | V 2x 64x512B  (swizzle: unit ^= row&7)
#define AQ 0
#define AK 65536
#define AV 131072
#define AT_TOT 196608
#define NT64 (N_/64)

__global__ void __launch_bounds__(512, 1) k_attn(const int* __restrict__ adj) {
    extern __shared__ char dsm[];
    unsigned sbase = smem_u32(dsm);
    int tid = threadIdx.x;
    int l = tid & 31, warp = tid >> 5;   // 16 warps
    int wm = warp & 7, wd = warp >> 3;
    int quad = l >> 2, qlane = l & 3;

    int m0 = blockIdx.x * 128;
    int p  = blockIdx.y;

    const bf16* gq = g_q16 + ((size_t)(p >> 1)*N_ + m0)*D_;
    const bf16* gk = g_k16 + (size_t)p*N_*D_;
    const bf16* gv = g_v16 + (size_t)p*N_*D_;

    // adj int2 pointers: rows (wm*16+quad) and (+8); per tile stride 32 int2, per n8 j: +j*4
    const int2* adj0 = (const int2*)(adj + ((size_t)p*N_ + m0 + wm*16 + quad    )*N_) + qlane;
    const int2* adj8 = (const int2*)(adj + ((size_t)p*N_ + m0 + wm*16 + quad + 8)*N_) + qlane;

    // ---- preload: one group = q + K(0) + V(0) ----
    #pragma unroll
    for (int it = 0; it < 8; it++) {
        int c = it*512 + tid;
        int row = c >> 5, seg = c & 31;
        unsigned off = (unsigned)(row*512 + ((seg ^ (row & 7)) << 4));
        CPA16(sbase + AQ + off, gq + (size_t)row*D_ + seg*8);
    }
    #pragma unroll
    for (int it = 0; it < 4; it++) {
        int c = it*512 + tid;
        int row = c >> 5, seg = c & 31;
        unsigned off = (unsigned)(row*512 + ((seg ^ (row & 7)) << 4));
        CPA16(sbase + AK + off, gk + (size_t)row*D_ + seg*8);
        CPA16(sbase + AV + off, gv + (size_t)row*D_ + seg*8);
    }
    CPA_COMMIT();

    float o[16][4];
    #pragma unroll
    for (int i=0;i<16;i++) { o[i][0]=0.f;o[i][1]=0.f;o[i][2]=0.f;o[i][3]=0.f; }
    float rs0 = 0.f, rs1 = 0.f;

    int rx = l & 7;
    unsigned qrow = sbase + AQ + (unsigned)((wm*16 + (l & 7) + ((l >> 3) & 1)*8) * 512);
    int uA = l >> 4;
    unsigned krow_off = (unsigned)(((l & 7) + ((l >> 4) & 1)*8) * 512);
    int uB = (l >> 3) & 1;
    unsigned vrow_off = (unsigned)((l & 15) * 512);
    int u0V = wd*16 + ((l >> 4) & 1);

    for (int t = 0; t < NT64; t++) {
        if (t + 1 < NT64) {
            const bf16* gk1 = gk + (size_t)(t+1)*64*D_;
            const bf16* gv1 = gv + (size_t)(t+1)*64*D_;
            unsigned kd = sbase + AK + (unsigned)((t+1) & 1)*32768u;
            unsigned vd = sbase + AV + (unsigned)((t+1) & 1)*32768u;
            #pragma unroll
            for (int it = 0; it < 4; it++) {
                int c = it*512 + tid;
                int row = c >> 5, seg = c & 31;
                unsigned off = (unsigned)(row*512 + ((seg ^ (row & 7)) << 4));
                CPA16(kd + off, gk1 + (size_t)row*D_ + seg*8);
                CPA16(vd + off, gv1 + (size_t)row*D_ + seg*8);
            }
            CPA_COMMIT();
            CPA_WAIT1();
        } else {
            CPA_WAIT0();
        }
        __syncthreads();

        // ---- adj -> bitmasks (2 regs) ----
        unsigned mm0 = 0, mm8 = 0;
        #pragma unroll
        for (int j = 0; j < 8; j++) {
            int2 v0 = adj0[t*32 + j*4];
            int2 v8 = adj8[t*32 + j*4];
            mm0 |= ((unsigned)(v0.x != 0)) << (2*j);
            mm0 |= ((unsigned)(v0.y != 0)) << (2*j + 1);
            mm8 |= ((unsigned)(v8.x != 0)) << (2*j);
            mm8 |= ((unsigned)(v8.y != 0)) << (2*j + 1);
        }

        // ---- S = q @ K^T : warp m16 x kv64, k=256 ----
        unsigned kbase = sbase + AK + (unsigned)(t & 1)*32768u + krow_off;
        float sc[8][4];
        #pragma unroll
        for (int i=0;i<8;i++){sc[i][0]=0.f;sc[i][1]=0.f;sc[i][2]=0.f;sc[i][3]=0.f;}
        #pragma unroll
        for (int ks = 0; ks < 16; ks++) {
            unsigned a0,a1,a2,a3;
            LDSM_X4(a0,a1,a2,a3, qrow + (unsigned)(((ks*2 + uA) ^ rx) << 4));
            #pragma unroll
            for (int g = 0; g < 4; g++) {
                unsigned b0,b1,b2,b3;
                LDSM_X4(b0,b1,b2,b3,
                        kbase + (unsigned)(g*16*512) + (unsigned)(((ks*2 + uB) ^ rx) << 4));
                MMA16816(sc[g*2  ], a0,a1,a2,a3, b0,b1);
                MMA16816(sc[g*2+1], a0,a1,a2,a3, b2,b3);
            }
        }

        // ---- mask + exp + rowsum + pack C-frags into A-frags ----
        unsigned pa[4][4];
        #pragma unroll
        for (int j = 0; j < 8; j++) {
            float e0 = (mm0 >> (2*j    )) & 1 ? __expf(sc[j][0]*0.0625f) : 0.f;
            float e1 = (mm0 >> (2*j + 1)) & 1 ? __expf(sc[j][1]*0.0625f) : 0.f;
            float e2 = (mm8 >> (2*j    )) & 1 ? __expf(sc[j][2]*0.0625f) : 0.f;
            float e3 = (mm8 >> (2*j + 1)) & 1 ? __expf(sc[j][3]*0.0625f) : 0.f;
            rs0 += e0 + e1;
            rs1 += e2 + e3;
            pa[j >> 1][(j & 1)*2    ] = pk2(e0, e1);
            pa[j >> 1][(j & 1)*2 + 1] = pk2(e2, e3);
        }

        // ---- O += P @ V : warp m16 x d128, k=64 (P from regs) ----
        unsigned vbase = sbase + AV + (unsigned)(t & 1)*32768u + vrow_off;
        #pragma unroll
        for (int ks2 = 0; ks2 < 4; ks2++) {
            unsigned vrow = vbase + (unsigned)(ks2*16*512);
            #pragma unroll
            for (int nt = 0; nt < 8; nt++) {
                unsigned b0,b1,b2,b3;
                LDSM_X4T(b0,b1,b2,b3, vrow + (unsigned)(((u0V + nt*2) ^ rx) << 4));
                MMA16816(o[nt*2  ], pa[ks2][0],pa[ks2][1],pa[ks2][2],pa[ks2][3], b0,b1);
                MMA16816(o[nt*2+1], pa[ks2][0],pa[ks2][1],pa[ks2][2],pa[ks2][3], b2,b3);
            }
        }
        __syncthreads();   // K/V buffer reads done before next-iter issue
    }

    // ---- normalize (rowsum complete per warp) + write ----
    rs0 += __shfl_xor_sync(0xffffffffu, rs0, 1);
    rs0 += __shfl_xor_sync(0xffffffffu, rs0, 2);
    rs1 += __shfl_xor_sync(0xffffffffu, rs1, 1);
    rs1 += __shfl_xor_sync(0xffffffffu, rs1, 2);
    float ia = rs0 > 0.f ? __fdividef(1.f, rs0) : 0.f;
    float ib = rs1 > 0.f ? __fdividef(1.f, rs1) : 0.f;

    bf16* d0 = g_h16 + ((size_t)((p >> 1)*N_ + m0 + wm*16 + quad))*(R_*D_) + (p & 1)*D_ + wd*128;
    bf16* d1 = d0 + (size_t)8*(R_*D_);
    #pragma unroll
    for (int nt = 0; nt < 16; nt++) {
        int col = nt*8 + qlane*2;
        *(unsigned*)(d0 + col) = pk2(o[nt][0]*ia, o[nt][1]*ia);
        *(unsigned*)(d1 + col) = pk2(o[nt][2]*ib, o[nt][3]*ib);
    }
}

// ============ h_fused GEMM + relu + residual + LN (mma.sync, proven) ============
__global__ void __launch_bounds__(256) k_fused16(
        const float* __restrict__ node_embed,
        const float* __restrict__ WF_b,
        const float* __restrict__ ln_g, const float* __restrict__ ln_b,
        float* __restrict__ out) {
    __shared__ bf16 As[64*40];
    __shared__ bf16 Bs[32*264];
    __shared__ float2 part[64][4];
    int tid = threadIdx.x;
    int l = tid & 31, warp = tid >> 5;
    int warp_m = warp & 1, warp_n = warp >> 1;
    int quad = l >> 2, qlane = l & 3;
    int m0 = blockIdx.x * 64;

    float acc[2][8][4];
    #pragma unroll
    for (int i=0;i<2;i++) for (int j=0;j<8;j++) for (int c=0;c<4;c++) acc[i][j][c]=0.f;

    int a_row = tid >> 2, a_seg = tid & 3;
    int b_row = tid >> 5, b_seg = tid & 31;

    int arow = (l & 7) + ((l >> 3) & 1) * 8;
    int acol = (l >> 4) * 8;
    unsigned a_base = smem_u32(As) + (unsigned)(((warp_m*32 + arow)*40 + acol) * 2);
    int lt = l & 15;
    unsigned b_base = smem_u32(Bs) + (unsigned)((lt*264 + warp_n*64) * 2);

    {
        *(uint4*)&As[a_row*40 + a_seg*8] =
            *(const uint4*)(g_h16 + (size_t)(m0+a_row)*(R_*D_) + a_seg*8);
        #pragma unroll
        for (int it=0; it<4; it++) {
            int rb = b_row + it*8;
            *(uint4*)&Bs[rb*264 + b_seg*8] =
                *(const uint4*)(g_wf16 + (size_t)rb*D_ + b_seg*8);
        }
    }
    __syncthreads();

    for (int c0 = 0; c0 < R_*D_; c0 += 32) {
        bool nxt = (c0 + 32 < R_*D_);
        uint4 pa0, pb[4];
        if (nxt) {
            pa0 = *(const uint4*)(g_h16 + (size_t)(m0+a_row)*(R_*D_) + c0+32 + a_seg*8);
            #pragma unroll
            for (int it=0; it<4; it++)
                pb[it] = *(const uint4*)(g_wf16 + (size_t)(c0+32+b_row+it*8)*D_ + b_seg*8);
        }
        #pragma unroll
        for (int ks = 0; ks < 2; ks++) {
            unsigned a0,a1,a2,a3;
            unsigned bfr[8][2];
            #pragma unroll
            for (int nt=0; nt<8; nt++) {
                unsigned addr = b_base + (unsigned)((ks*16*264 + nt*8) * 2);
                LDSM_X2T(bfr[nt][0], bfr[nt][1], addr);
            }
            #pragma unroll
            for (int mt=0; mt<2; mt++) {
                unsigned addr = a_base + (unsigned)((mt*16*40 + ks*16) * 2);
                LDSM_X4(a0,a1,a2,a3, addr);
                #pragma unroll
                for (int nt=0; nt<8; nt++)
                    MMA16816(acc[mt][nt], a0,a1,a2,a3, bfr[nt][0], bfr[nt][1]);
            }
        }
        __syncthreads();
        if (nxt) {
            *(uint4*)&As[a_row*40 + a_seg*8] = pa0;
            #pragma unroll
            for (int it=0; it<4; it++)
                *(uint4*)&Bs[(b_row+it*8)*264 + b_seg*8] = pb[it];
            __syncthreads();
        }
    }

    #pragma unroll
    for (int mt=0; mt<2; mt++) {
        #pragma unroll
        for (int half=0; half<2; half++) {
            int row_l = warp_m*32 + mt*16 + quad + half*8;
            int grow = m0 + row_l;
            float s = 0.f, sq = 0.f;
            #pragma unroll
            for (int nt=0; nt<8; nt++) {
                int col = warp_n*64 + nt*8 + qlane*2;
                float2 bb = *(const float2*)(WF_b + col);
                float h0 = acc[mt][nt][half*2+0] + bb.x; h0 = h0 > 0.f ? h0 : 0.f;
                float h1 = acc[mt][nt][half*2+1] + bb.y; h1 = h1 > 0.f ? h1 : 0.f;
                float2 ne = *(const float2*)(node_embed + (size_t)grow*D_ + col);
                float y0 = ne.x + h0, y1 = ne.y + h1;
                acc[mt][nt][half*2+0] = y0;
                acc[mt][nt][half*2+1] = y1;
                s += y0 + y1;
                sq = fmaf(y0, y0, fmaf(y1, y1, sq));
            }
            s  += __shfl_xor_sync(0xffffffffu, s, 1);
            s  += __shfl_xor_sync(0xffffffffu, s, 2);
            sq += __shfl_xor_sync(0xffffffffu, sq, 1);
            sq += __shfl_xor_sync(0xffffffffu, sq, 2);
            if (qlane == 0) part[row_l][warp_n] = make_float2(s, sq);
        }
    }
    __syncthreads();
    #pragma unroll
    for (int mt=0; mt<2; mt++) {
        #pragma unroll
        for (int half=0; half<2; half++) {
            int row_l = warp_m*32 + mt*16 + quad + half*8;
            int grow = m0 + row_l;
            float s = 0.f, sq = 0.f;
            #pragma unroll
            for (int w=0; w<4; w++) { float2 pp = part[row_l][w]; s += pp.x; sq += pp.y; }
            float mu = s * (1.0f/256.0f);
            float var = sq * (1.0f/256.0f) - mu*mu;
            float rstd = rsqrtf(var + 1e-5f);
            #pragma unroll
            for (int nt=0; nt<8; nt++) {
                int col = warp_n*64 + nt*8 + qlane*2;
                float2 gg = *(const float2*)(ln_g + col);
                float2 bb = *(const float2*)(ln_b + col);
                float y0 = acc[mt][nt][half*2+0];
                float y1 = acc[mt][nt][half*2+1];
                float2 o;
                o.x = (y0 - mu) * rstd * gg.x + bb.x;
                o.y = (y1 - mu) * rstd * gg.y + bb.y;
                *(float2*)(out + (size_t)grow*D_ + col) = o;
            }
        }
    }
}

// ---------------- launch ----------------
extern "C" void kernel_launch(void* const* d_in, const int* in_sizes, int n_in,
                              void* d_out, int out_size) {
    const float* node_embed = (const float*)d_in[0];
    const float* input_x    = (const float*)d_in[1];
    const int*   adj        = (const int*)  d_in[2];
    const float* WQi_w      = (const float*)d_in[3];
    const float* WQi_b      = (const float*)d_in[4];
    const float* WQ_w       = (const float*)d_in[5];
    const float* WQ_b       = (const float*)d_in[6];
    const float* WK_w       = (const float*)d_in[7];
    const float* WK_b       = (const float*)d_in[8];
    const float* WV_w       = (const float*)d_in[9];
    const float* WV_b       = (const float*)d_in[10];
    const float* WF_w       = (const float*)d_in[11];
    const float* WF_b       = (const float*)d_in[12];
    const float* ln_g       = (const float*)d_in[13];
    const float* ln_b       = (const float*)d_in[14];
    float* out = (float*)d_out;

    cudaFuncSetAttribute(k_attn, cudaFuncAttributeMaxDynamicSharedMemorySize, AT_TOT);

    k_x1      <<<B_, F_>>>(input_x, WQi_w, WQi_b);
    k_cvtw    <<<1216, 256>>>(WQ_w, WK_w, WV_w, WF_w);
    k_qkv16   <<<dim3(10, 128), 256>>>(node_embed, WQ_b, WK_b, WV_b);
    k_attn    <<<dim3(16, B_*R_), 512, AT_TOT>>>(adj);
    k_fused16 <<<M_TOT/64, 256>>>(node_embed, WF_b, ln_g, ln_b, out);
}

// round 14
// speedup vs baseline: 1.7056x; 1.7056x over previous
#include <cuda_runtime.h>
#include <cuda_bf16.h>
#include <math.h>

#define B_ 8
#define N_ 2048
#define D_ 256
#define F_ 128
#define R_ 2
#define KQ 384            // D_+F_
#define M_TOT (B_*N_)     // 16384

typedef __nv_bfloat16 bf16;
typedef __nv_bfloat162 bf162;

// ---------------- scratch ----------------
__device__ float g_x1[B_*F_];
__device__ bf16  g_q16[(size_t)M_TOT*D_];
__device__ bf16  g_k16[(size_t)B_*R_*N_*D_];
__device__ bf16  g_v16[(size_t)B_*R_*N_*D_];
__device__ bf16  g_h16[(size_t)M_TOT*R_*D_];
__device__ bf16  g_wq16[KQ*D_];
__device__ bf16  g_wk16[R_*KQ*D_];
__device__ bf16  g_wv16[R_*KQ*D_];
__device__ bf16  g_wf16[R_*D_*D_];
__device__ bf16  g_wT[5*D_*KQ];                 // transposed q/k0/k1/v0/v1 weights [c][n][k]

// ---------------- PTX helpers ----------------
__device__ __forceinline__ unsigned smem_u32(const void* p) {
    return (unsigned)__cvta_generic_to_shared(p);
}
#define LDSM_X4(r0,r1,r2,r3,addr) \
    asm volatile("ldmatrix.sync.aligned.m8n8.x4.shared.b16 {%0,%1,%2,%3}, [%4];" \
        : "=r"(r0),"=r"(r1),"=r"(r2),"=r"(r3) : "r"(addr))
#define LDSM_X4T(r0,r1,r2,r3,addr) \
    asm volatile("ldmatrix.sync.aligned.m8n8.x4.trans.shared.b16 {%0,%1,%2,%3}, [%4];" \
        : "=r"(r0),"=r"(r1),"=r"(r2),"=r"(r3) : "r"(addr))
#define LDSM_X2T(r0,r1,addr) \
    asm volatile("ldmatrix.sync.aligned.m8n8.x2.trans.shared.b16 {%0,%1}, [%2];" \
        : "=r"(r0),"=r"(r1) : "r"(addr))
#define MMA16816(c,a0,a1,a2,a3,b0,b1) \
    asm volatile("mma.sync.aligned.m16n8k16.row.col.f32.bf16.bf16.f32 " \
        "{%0,%1,%2,%3},{%4,%5,%6,%7},{%8,%9},{%0,%1,%2,%3};" \
        : "+f"(c[0]),"+f"(c[1]),"+f"(c[2]),"+f"(c[3]) \
        : "r"(a0),"r"(a1),"r"(a2),"r"(a3),"r"(b0),"r"(b1))
#define CPA16(s,g) asm volatile("cp.async.cg.shared.global [%0], [%1], 16;" :: "r"(s), "l"(g))
#define CPA_COMMIT() asm volatile("cp.async.commit_group;" ::: "memory")
#define CPA_WAIT1() asm volatile("cp.async.wait_group 1;" ::: "memory")

static __device__ __forceinline__ unsigned pk2(float a, float b) {
    bf162 t = __float22bfloat162_rn(make_float2(a, b));
    return *(unsigned*)&t;
}

// ---------------- x1 ----------------
__global__ void k_x1(const float* __restrict__ input_x,
                     const float* __restrict__ Ww,
                     const float* __restrict__ Wb) {
    __shared__ float row[F_];
    int b = blockIdx.x, j = threadIdx.x;
    row[j] = input_x[b*F_ + j];
    __syncthreads();
    float s = Wb[j];
    #pragma unroll 4
    for (int c = 0; c < F_; c++) s = fmaf(row[c], Ww[c*F_ + j], s);
    g_x1[b*F_ + j] = s;
}

// ---------------- weights to bf16 ----------------
__global__ void k_cvtw(const float* __restrict__ wq, const float* __restrict__ wk,
                       const float* __restrict__ wv, const float* __restrict__ wf) {
    int i = blockIdx.x * blockDim.x + threadIdx.x;
    int e = i * 2;
    const int SQ = KQ*D_, SK = R_*KQ*D_, SF = R_*D_*D_;
    if (e < SQ) {
        *(bf162*)(g_wq16 + e) = __float22bfloat162_rn(*(const float2*)(wq + e));
    } else if (e < SQ + SK) {
        int o = e - SQ;
        *(bf162*)(g_wk16 + o) = __float22bfloat162_rn(*(const float2*)(wk + o));
    } else if (e < SQ + 2*SK) {
        int o = e - SQ - SK;
        *(bf162*)(g_wv16 + o) = __float22bfloat162_rn(*(const float2*)(wv + o));
    } else if (e < SQ + 2*SK + SF) {
        int o = e - SQ - 2*SK;
        *(bf162*)(g_wf16 + o) = __float22bfloat162_rn(*(const float2*)(wf + o));
    }
}

// ---------------- transpose q/k/v weights: [k][n] -> [n][k] per chunk ----------------
__global__ void k_wT() {
    __shared__ bf16 tile[32][33];
    int c = blockIdx.z;               // 0..4
    int k0 = blockIdx.x * 32, n0 = blockIdx.y * 32;
    int tx = threadIdx.x, ty = threadIdx.y;   // 32 x 8
    const bf16* src;
    if (c == 0)      src = g_wq16;
    else if (c <= 2) src = g_wk16 + (size_t)(c-1)*KQ*D_;
    else             src = g_wv16 + (size_t)(c-3)*KQ*D_;
    bf16* dst = g_wT + (size_t)c*D_*KQ;
    #pragma unroll
    for (int i = 0; i < 4; i++)
        tile[ty + i*8][tx] = src[(size_t)(k0 + ty + i*8)*D_ + n0 + tx];
    __syncthreads();
    #pragma unroll
    for (int i = 0; i < 4; i++)
        dst[(size_t)(n0 + ty + i*8)*KQ + k0 + tx] = tile[tx][ty + i*8];
}

// inline concat loader: 8 bf16 of [node_embed | x1] row m, cols c..c+7
__device__ __forceinline__ uint4 load_cat8(const float* __restrict__ ne, int m, int c) {
    float4 f0, f1;
    if (c < D_) {
        const float* p = ne + (size_t)m*D_ + c;
        f0 = *(const float4*)p; f1 = *(const float4*)(p + 4);
    } else {
        const float* p = g_x1 + (size_t)(m >> 11)*F_ + (c - D_);
        f0 = *(const float4*)p; f1 = *(const float4*)(p + 4);
    }
    uint4 r;
    r.x = pk2(f0.x, f0.y); r.y = pk2(f0.z, f0.w);
    r.z = pk2(f1.x, f1.y); r.w = pk2(f1.z, f1.w);
    return r;
}

// ============ qkv GEMM: CTA 128x128, 8 warps 64x32; B n-major via X4 ============
__global__ void __launch_bounds__(256) k_qkv16(
        const float* __restrict__ node_embed,
        const float* __restrict__ WQ_b, const float* __restrict__ WK_b,
        const float* __restrict__ WV_b) {
    __shared__ bf16 As[128*40];       // [m][k32] pad 40
    __shared__ bf16 Bs[128*40];       // [n128][k32] pad 40
    int tid = threadIdx.x;
    int l = tid & 31, warp = tid >> 5;
    int warp_m = warp & 1, warp_n = warp >> 1;
    int quad = l >> 2, qlane = l & 3;

    int bn = blockIdx.x;
    int m0 = blockIdx.y * 128;
    int chunk = bn >> 1;
    int j0 = (bn & 1) * 128;

    const bf16* WT = g_wT + (size_t)chunk*D_*KQ + (size_t)j0*KQ;
    const float* bias;
    if (chunk == 0)      bias = WQ_b;
    else if (chunk <= 2) bias = WK_b + (chunk-1)*D_;
    else                 bias = WV_b + (chunk-3)*D_;

    float acc[4][4][4];
    #pragma unroll
    for (int i=0;i<4;i++) for (int j=0;j<4;j++) for (int c=0;c<4;c++) acc[i][j][c]=0.f;

    int a_row = tid >> 2, a_seg = tid & 3;    // A: rows tid>>2 (+64), segs 0..3
    // B: same decomposition over 128 n-rows x 4 k-segs

    int arow = (l & 7) + ((l >> 3) & 1) * 8;
    int acol = (l >> 4) * 8;
    unsigned a_base = smem_u32(As) + (unsigned)(((warp_m*64 + arow)*40 + acol) * 2);
    unsigned b_base = smem_u32(Bs) +
        (unsigned)(((warp_n*32 + (l & 7) + ((l >> 4) & 1)*8)*40 + ((l >> 3) & 1)*8) * 2);

    {
        #pragma unroll
        for (int it=0; it<2; it++) {
            int r = a_row + it*64;
            *(uint4*)&As[r*40 + a_seg*8] = load_cat8(node_embed, m0 + r, a_seg*8);
            *(uint4*)&Bs[r*40 + a_seg*8] =
                *(const uint4*)(WT + (size_t)r*KQ + a_seg*8);
        }
    }
    __syncthreads();

    for (int c0 = 0; c0 < KQ; c0 += 32) {
        bool nxt = (c0 + 32 < KQ);
        uint4 pa0,pa1,pb0,pb1;
        if (nxt) {
            pa0 = load_cat8(node_embed, m0 + a_row,      c0+32 + a_seg*8);
            pa1 = load_cat8(node_embed, m0 + a_row + 64, c0+32 + a_seg*8);
            pb0 = *(const uint4*)(WT + (size_t)(a_row   )*KQ + c0+32 + a_seg*8);
            pb1 = *(const uint4*)(WT + (size_t)(a_row+64)*KQ + c0+32 + a_seg*8);
        }
        #pragma unroll
        for (int ks = 0; ks < 2; ks++) {
            unsigned bfr[4][2];
            #pragma unroll
            for (int nt16 = 0; nt16 < 2; nt16++) {
                unsigned b0,b1,b2,b3;
                LDSM_X4(b0,b1,b2,b3,
                        b_base + (unsigned)((nt16*16*40 + ks*16) * 2));
                bfr[nt16*2  ][0] = b0; bfr[nt16*2  ][1] = b1;
                bfr[nt16*2+1][0] = b2; bfr[nt16*2+1][1] = b3;
            }
            #pragma unroll
            for (int mt=0; mt<4; mt++) {
                unsigned a0,a1,a2,a3;
                unsigned addr = a_base + (unsigned)((mt*16*40 + ks*16) * 2);
                LDSM_X4(a0,a1,a2,a3, addr);
                #pragma unroll
                for (int nt=0; nt<4; nt++)
                    MMA16816(acc[mt][nt], a0,a1,a2,a3, bfr[nt][0], bfr[nt][1]);
            }
        }
        __syncthreads();
        if (nxt) {
            *(uint4*)&As[(a_row   )*40 + a_seg*8] = pa0;
            *(uint4*)&As[(a_row+64)*40 + a_seg*8] = pa1;
            *(uint4*)&Bs[(a_row   )*40 + a_seg*8] = pb0;
            *(uint4*)&Bs[(a_row+64)*40 + a_seg*8] = pb1;
            __syncthreads();
        }
    }

    #pragma unroll
    for (int mt=0; mt<4; mt++) {
        #pragma unroll
        for (int half=0; half<2; half++) {
            int i = m0 + warp_m*64 + mt*16 + quad + half*8;
            int bb = i >> 11, ntok = i & (N_-1);
            #pragma unroll
            for (int nt=0; nt<4; nt++) {
                int jj = j0 + warp_n*32 + nt*8 + qlane*2;
                float2 bv = *(const float2*)(bias + jj);
                float v0 = acc[mt][nt][half*2+0] + bv.x;
                float v1 = acc[mt][nt][half*2+1] + bv.y;
                bf16* dst;
                if (chunk == 0)      dst = g_q16 + (size_t)i*D_ + jj;
                else if (chunk <= 2) dst = g_k16 + ((size_t)(bb*R_ + (chunk-1))*N_ + ntok)*D_ + jj;
                else                 dst = g_v16 + ((size_t)(bb*R_ + (chunk-3))*N_ + ntok)*D_ + jj;
                *(bf162*)dst = __float22bfloat162_rn(make_float2(v0, v1));
            }
        }
    }
}

// ============ fused attention (R11-proven): 64 q-rows/CTA, 256 thr, 2 CTAs/SM ======
#define AT_Q   0
#define AT_K   33792
#define AT_V   67584
#define AT_P   101376
#define AT_RS  110592
#define AT_TOT 111104
#define NT64   (N_/64)

__global__ void __launch_bounds__(256, 2) k_attn(const int* __restrict__ adj) {
    extern __shared__ char dsm[];
    unsigned sbase = smem_u32(dsm);
    int tid = threadIdx.x;
    int l = tid & 31, warp = tid >> 5;   // 8 warps
    int wm = warp & 3, wd = warp >> 2;
    int quad = l >> 2, qlane = l & 3;

    int m0 = blockIdx.x * 64;
    int p  = blockIdx.y;

    const bf16* gq = g_q16 + ((size_t)(p >> 1)*N_ + m0)*D_;
    const bf16* gk = g_k16 + (size_t)p*N_*D_;
    const bf16* gv = g_v16 + (size_t)p*N_*D_;
    const int2* adj0 = (const int2*)(adj + ((size_t)p*N_ + m0 + wm*16 + quad    )*N_ + wd*32) + qlane;
    const int2* adj8 = (const int2*)(adj + ((size_t)p*N_ + m0 + wm*16 + quad + 8)*N_ + wd*32) + qlane;

    #pragma unroll
    for (int it = 0; it < 8; it++) {
        int c = it*256 + tid;
        int row = c >> 5, seg = c & 31;
        CPA16(sbase + AT_Q + (unsigned)(row*528 + seg*16), gq + (size_t)row*D_ + seg*8);
    }
    #pragma unroll
    for (int it = 0; it < 8; it++) {
        int c = it*256 + tid;
        int row = c >> 5, seg = c & 31;
        CPA16(sbase + AT_K + (unsigned)(row*528 + seg*16), gk + (size_t)row*D_ + seg*8);
    }
    CPA_COMMIT();
    #pragma unroll
    for (int it = 0; it < 8; it++) {
        int c = it*256 + tid;
        int row = c >> 5, seg = c & 31;
        CPA16(sbase + AT_V + (unsigned)(row*528 + seg*16), gv + (size_t)row*D_ + seg*8);
    }
    CPA_COMMIT();

    float o[16][4];
    #pragma unroll
    for (int i=0;i<16;i++) { o[i][0]=0.f;o[i][1]=0.f;o[i][2]=0.f;o[i][3]=0.f; }
    float rs0 = 0.f, rs1 = 0.f;

    unsigned qa = sbase + AT_Q +
        (unsigned)(((wm*16 + (l & 7) + ((l >> 3) & 1)*8)*264 + (l >> 4)*8) * 2);
    unsigned kbb = sbase + AT_K +
        (unsigned)(((wd*32 + (l & 7) + ((l >> 4) & 1)*8)*264 + ((l >> 3) & 1)*8) * 2);
    unsigned pa = sbase + AT_P +
        (unsigned)(((wm*16 + (l & 7) + ((l >> 3) & 1)*8)*72 + (l >> 4)*8) * 2);
    unsigned vbb = sbase + AT_V +
        (unsigned)(((l & 15)*264 + wd*128 + ((l >> 4) & 1)*8) * 2);

    bf16* Psm = (bf16*)(dsm + AT_P);
    float* rsm = (float*)(dsm + AT_RS);

    for (int t = 0; t < NT64; t++) {
        CPA_WAIT1();
        __syncthreads();

        int2 am[8];
        #pragma unroll
        for (int nt = 0; nt < 4; nt++) {
            am[nt]     = adj0[t*32 + nt*4];
            am[4 + nt] = adj8[t*32 + nt*4];
        }

        float sc[4][4];
        #pragma unroll
        for (int i=0;i<4;i++){sc[i][0]=0.f;sc[i][1]=0.f;sc[i][2]=0.f;sc[i][3]=0.f;}
        #pragma unroll
        for (int ks = 0; ks < 16; ks++) {
            unsigned a0,a1,a2,a3;
            LDSM_X4(a0,a1,a2,a3, qa + (unsigned)(ks*32));
            #pragma unroll
            for (int nt16 = 0; nt16 < 2; nt16++) {
                unsigned b0,b1,b2,b3;
                LDSM_X4(b0,b1,b2,b3, kbb + (unsigned)((nt16*16*264 + ks*16) * 2));
                MMA16816(sc[nt16*2  ], a0,a1,a2,a3, b0,b1);
                MMA16816(sc[nt16*2+1], a0,a1,a2,a3, b2,b3);
            }
        }

        {
            int r0 = wm*16 + quad;
            #pragma unroll
            for (int nt = 0; nt < 4; nt++) {
                float e00 = am[nt].x   ? __expf(sc[nt][0]*0.0625f) : 0.f;
                float e01 = am[nt].y   ? __expf(sc[nt][1]*0.0625f) : 0.f;
                float e10 = am[4+nt].x ? __expf(sc[nt][2]*0.0625f) : 0.f;
                float e11 = am[4+nt].y ? __expf(sc[nt][3]*0.0625f) : 0.f;
                rs0 += e00 + e01;
                rs1 += e10 + e11;
                int col = wd*32 + nt*8 + qlane*2;
                *(unsigned*)(Psm + r0*72 + col)     = pk2(e00, e01);
                *(unsigned*)(Psm + (r0+8)*72 + col) = pk2(e10, e11);
            }
        }
        __syncthreads();

        if (t + 1 < NT64) {
            const bf16* gk1 = gk + (size_t)(t+1)*64*D_;
            #pragma unroll
            for (int it = 0; it < 8; it++) {
                int c = it*256 + tid;
                int row = c >> 5, seg = c & 31;
                CPA16(sbase + AT_K + (unsigned)(row*528 + seg*16),
                      gk1 + (size_t)row*D_ + seg*8);
            }
        }
        CPA_COMMIT();

        CPA_WAIT1();
        __syncthreads();

        #pragma unroll
        for (int ks2 = 0; ks2 < 4; ks2++) {
            unsigned a0,a1,a2,a3;
            LDSM_X4(a0,a1,a2,a3, pa + (unsigned)(ks2*32));
            #pragma unroll
            for (int nt16 = 0; nt16 < 8; nt16++) {
                unsigned b0,b1,b2,b3;
                LDSM_X4T(b0,b1,b2,b3, vbb + (unsigned)((ks2*16*264 + nt16*16) * 2));
                MMA16816(o[nt16*2  ], a0,a1,a2,a3, b0,b1);
                MMA16816(o[nt16*2+1], a0,a1,a2,a3, b2,b3);
            }
        }
        __syncthreads();

        if (t + 1 < NT64) {
            const bf16* gv1 = gv + (size_t)(t+1)*64*D_;
            #pragma unroll
            for (int it = 0; it < 8; it++) {
                int c = it*256 + tid;
                int row = c >> 5, seg = c & 31;
                CPA16(sbase + AT_V + (unsigned)(row*528 + seg*16),
                      gv1 + (size_t)row*D_ + seg*8);
            }
        }
        CPA_COMMIT();
    }

    rs0 += __shfl_xor_sync(0xffffffffu, rs0, 1);
    rs0 += __shfl_xor_sync(0xffffffffu, rs0, 2);
    rs1 += __shfl_xor_sync(0xffffffffu, rs1, 1);
    rs1 += __shfl_xor_sync(0xffffffffu, rs1, 2);
    if (qlane == 0) {
        rsm[wd*64 + wm*16 + quad]     = rs0;
        rsm[wd*64 + wm*16 + quad + 8] = rs1;
    }
    __syncthreads();

    {
        int r = wm*16 + quad;
        float ta = rsm[r]     + rsm[64 + r];
        float tb = rsm[r + 8] + rsm[64 + r + 8];
        float ia = ta > 0.f ? __fdividef(1.f, ta) : 0.f;
        float ib = tb > 0.f ? __fdividef(1.f, tb) : 0.f;
        bf16* d0 = g_h16 + ((size_t)((p >> 1)*N_ + m0 + r))*(R_*D_) + (p & 1)*D_ + wd*128;
        bf16* d1 = d0 + (size_t)8*(R_*D_);
        #pragma unroll
        for (int nt = 0; nt < 16; nt++) {
            int col = nt*8 + qlane*2;
            *(unsigned*)(d0 + col) = pk2(o[nt][0]*ia, o[nt][1]*ia);
            *(unsigned*)(d1 + col) = pk2(o[nt][2]*ib, o[nt][3]*ib);
        }
    }
}

// ============ h_fused GEMM + relu + residual + LN (mma.sync, proven) ============
__global__ void __launch_bounds__(256) k_fused16(
        const float* __restrict__ node_embed,
        const float* __restrict__ WF_b,
        const float* __restrict__ ln_g, const float* __restrict__ ln_b,
        float* __restrict__ out) {
    __shared__ bf16 As[64*40];
    __shared__ bf16 Bs[32*264];
    __shared__ float2 part[64][4];
    int tid = threadIdx.x;
    int l = tid & 31, warp = tid >> 5;
    int warp_m = warp & 1, warp_n = warp >> 1;
    int quad = l >> 2, qlane = l & 3;
    int m0 = blockIdx.x * 64;

    float acc[2][8][4];
    #pragma unroll
    for (int i=0;i<2;i++) for (int j=0;j<8;j++) for (int c=0;c<4;c++) acc[i][j][c]=0.f;

    int a_row = tid >> 2, a_seg = tid & 3;
    int b_row = tid >> 5, b_seg = tid & 31;

    int arow = (l & 7) + ((l >> 3) & 1) * 8;
    int acol = (l >> 4) * 8;
    unsigned a_base = smem_u32(As) + (unsigned)(((warp_m*32 + arow)*40 + acol) * 2);
    int lt = l & 15;
    unsigned b_base = smem_u32(Bs) + (unsigned)((lt*264 + warp_n*64) * 2);

    {
        *(uint4*)&As[a_row*40 + a_seg*8] =
            *(const uint4*)(g_h16 + (size_t)(m0+a_row)*(R_*D_) + a_seg*8);
        #pragma unroll
        for (int it=0; it<4; it++) {
            int rb = b_row + it*8;
            *(uint4*)&Bs[rb*264 + b_seg*8] =
                *(const uint4*)(g_wf16 + (size_t)rb*D_ + b_seg*8);
        }
    }
    __syncthreads();

    for (int c0 = 0; c0 < R_*D_; c0 += 32) {
        bool nxt = (c0 + 32 < R_*D_);
        uint4 pa0, pb[4];
        if (nxt) {
            pa0 = *(const uint4*)(g_h16 + (size_t)(m0+a_row)*(R_*D_) + c0+32 + a_seg*8);
            #pragma unroll
            for (int it=0; it<4; it++)
                pb[it] = *(const uint4*)(g_wf16 + (size_t)(c0+32+b_row+it*8)*D_ + b_seg*8);
        }
        #pragma unroll
        for (int ks = 0; ks < 2; ks++) {
            unsigned a0,a1,a2,a3;
            unsigned bfr[8][2];
            #pragma unroll
            for (int nt=0; nt<8; nt++) {
                unsigned addr = b_base + (unsigned)((ks*16*264 + nt*8) * 2);
                LDSM_X2T(bfr[nt][0], bfr[nt][1], addr);
            }
            #pragma unroll
            for (int mt=0; mt<2; mt++) {
                unsigned addr = a_base + (unsigned)((mt*16*40 + ks*16) * 2);
                LDSM_X4(a0,a1,a2,a3, addr);
                #pragma unroll
                for (int nt=0; nt<8; nt++)
                    MMA16816(acc[mt][nt], a0,a1,a2,a3, bfr[nt][0], bfr[nt][1]);
            }
        }
        __syncthreads();
        if (nxt) {
            *(uint4*)&As[a_row*40 + a_seg*8] = pa0;
            #pragma unroll
            for (int it=0; it<4; it++)
                *(uint4*)&Bs[(b_row+it*8)*264 + b_seg*8] = pb[it];
            __syncthreads();
        }
    }

    #pragma unroll
    for (int mt=0; mt<2; mt++) {
        #pragma unroll
        for (int half=0; half<2; half++) {
            int row_l = warp_m*32 + mt*16 + quad + half*8;
            int grow = m0 + row_l;
            float s = 0.f, sq = 0.f;
            #pragma unroll
            for (int nt=0; nt<8; nt++) {
                int col = warp_n*64 + nt*8 + qlane*2;
                float2 bb = *(const float2*)(WF_b + col);
                float h0 = acc[mt][nt][half*2+0] + bb.x; h0 = h0 > 0.f ? h0 : 0.f;
                float h1 = acc[mt][nt][half*2+1] + bb.y; h1 = h1 > 0.f ? h1 : 0.f;
                float2 ne = *(const float2*)(node_embed + (size_t)grow*D_ + col);
                float y0 = ne.x + h0, y1 = ne.y + h1;
                acc[mt][nt][half*2+0] = y0;
                acc[mt][nt][half*2+1] = y1;
                s += y0 + y1;
                sq = fmaf(y0, y0, fmaf(y1, y1, sq));
            }
            s  += __shfl_xor_sync(0xffffffffu, s, 1);
            s  += __shfl_xor_sync(0xffffffffu, s, 2);
            sq += __shfl_xor_sync(0xffffffffu, sq, 1);
            sq += __shfl_xor_sync(0xffffffffu, sq, 2);
            if (qlane == 0) part[row_l][warp_n] = make_float2(s, sq);
        }
    }
    __syncthreads();
    #pragma unroll
    for (int mt=0; mt<2; mt++) {
        #pragma unroll
        for (int half=0; half<2; half++) {
            int row_l = warp_m*32 + mt*16 + quad + half*8;
            int grow = m0 + row_l;
            float s = 0.f, sq = 0.f;
            #pragma unroll
            for (int w=0; w<4; w++) { float2 pp = part[row_l][w]; s += pp.x; sq += pp.y; }
            float mu = s * (1.0f/256.0f);
            float var = sq * (1.0f/256.0f) - mu*mu;
            float rstd = rsqrtf(var + 1e-5f);
            #pragma unroll
            for (int nt=0; nt<8; nt++) {
                int col = warp_n*64 + nt*8 + qlane*2;
                float2 gg = *(const float2*)(ln_g + col);
                float2 bb = *(const float2*)(ln_b + col);
                float y0 = acc[mt][nt][half*2+0];
                float y1 = acc[mt][nt][half*2+1];
                float2 o;
                o.x = (y0 - mu) * rstd * gg.x + bb.x;
                o.y = (y1 - mu) * rstd * gg.y + bb.y;
                *(float2*)(out + (size_t)grow*D_ + col) = o;
            }
        }
    }
}

// ---------------- launch ----------------
extern "C" void kernel_launch(void* const* d_in, const int* in_sizes, int n_in,
                              void* d_out, int out_size) {
    const float* node_embed = (const float*)d_in[0];
    const float* input_x    = (const float*)d_in[1];
    const int*   adj        = (const int*)  d_in[2];
    const float* WQi_w      = (const float*)d_in[3];
    const float* WQi_b      = (const float*)d_in[4];
    const float* WQ_w       = (const float*)d_in[5];
    const float* WQ_b       = (const float*)d_in[6];
    const float* WK_w       = (const float*)d_in[7];
    const float* WK_b       = (const float*)d_in[8];
    const float* WV_w       = (const float*)d_in[9];
    const float* WV_b       = (const float*)d_in[10];
    const float* WF_w       = (const float*)d_in[11];
    const float* WF_b       = (const float*)d_in[12];
    const float* ln_g       = (const float*)d_in[13];
    const float* ln_b       = (const float*)d_in[14];
    float* out = (float*)d_out;

    cudaFuncSetAttribute(k_attn, cudaFuncAttributeMaxDynamicSharedMemorySize, AT_TOT);

    k_x1      <<<B_, F_>>>(input_x, WQi_w, WQi_b);
    k_cvtw    <<<1216, 256>>>(WQ_w, WK_w, WV_w, WF_w);
    k_wT      <<<dim3(KQ/32, D_/32, 5), dim3(32, 8)>>>();
    k_qkv16   <<<dim3(10, 128), 256>>>(node_embed, WQ_b, WK_b, WV_b);
    k_attn    <<<dim3(32, B_*R_), 256, AT_TOT>>>(adj);
    k_fused16 <<<M_TOT/64, 256>>>(node_embed, WF_b, ln_g, ln_b, out);
}

// round 15
// speedup vs baseline: 1.7659x; 1.0354x over previous
#include <cuda_runtime.h>
#include <cuda_bf16.h>
#include <math.h>

#define B_ 8
#define N_ 2048
#define D_ 256
#define F_ 128
#define R_ 2
#define KQ 384            // D_+F_
#define M_TOT (B_*N_)     // 16384

typedef __nv_bfloat16 bf16;
typedef __nv_bfloat162 bf162;

// ---------------- scratch ----------------
__device__ float g_x1[B_*F_];
__device__ bf16  g_q16[(size_t)M_TOT*D_];
__device__ bf16  g_k16[(size_t)B_*R_*N_*D_];
__device__ bf16  g_v16[(size_t)B_*R_*N_*D_];
__device__ bf16  g_h16[(size_t)M_TOT*R_*D_];
__device__ bf16  g_wq16[KQ*D_];
__device__ bf16  g_wk16[R_*KQ*D_];
__device__ bf16  g_wv16[R_*KQ*D_];
__device__ bf16  g_wf16[R_*D_*D_];

// ---------------- PTX helpers ----------------
__device__ __forceinline__ unsigned smem_u32(const void* p) {
    return (unsigned)__cvta_generic_to_shared(p);
}
#define LDSM_X4(r0,r1,r2,r3,addr) \
    asm volatile("ldmatrix.sync.aligned.m8n8.x4.shared.b16 {%0,%1,%2,%3}, [%4];" \
        : "=r"(r0),"=r"(r1),"=r"(r2),"=r"(r3) : "r"(addr))
#define LDSM_X4T(r0,r1,r2,r3,addr) \
    asm volatile("ldmatrix.sync.aligned.m8n8.x4.trans.shared.b16 {%0,%1,%2,%3}, [%4];" \
        : "=r"(r0),"=r"(r1),"=r"(r2),"=r"(r3) : "r"(addr))
#define LDSM_X2T(r0,r1,addr) \
    asm volatile("ldmatrix.sync.aligned.m8n8.x2.trans.shared.b16 {%0,%1}, [%2];" \
        : "=r"(r0),"=r"(r1) : "r"(addr))
#define MMA16816(c,a0,a1,a2,a3,b0,b1) \
    asm volatile("mma.sync.aligned.m16n8k16.row.col.f32.bf16.bf16.f32 " \
        "{%0,%1,%2,%3},{%4,%5,%6,%7},{%8,%9},{%0,%1,%2,%3};" \
        : "+f"(c[0]),"+f"(c[1]),"+f"(c[2]),"+f"(c[3]) \
        : "r"(a0),"r"(a1),"r"(a2),"r"(a3),"r"(b0),"r"(b1))
#define CPA16(s,g) asm volatile("cp.async.cg.shared.global [%0], [%1], 16;" :: "r"(s), "l"(g))
#define CPA_COMMIT() asm volatile("cp.async.commit_group;" ::: "memory")
#define CPA_WAIT1() asm volatile("cp.async.wait_group 1;" ::: "memory")

static __device__ __forceinline__ unsigned pk2(float a, float b) {
    bf162 t = __float22bfloat162_rn(make_float2(a, b));
    return *(unsigned*)&t;
}

// ---------------- x1 ----------------
__global__ void k_x1(const float* __restrict__ input_x,
                     const float* __restrict__ Ww,
                     const float* __restrict__ Wb) {
    __shared__ float row[F_];
    int b = blockIdx.x, j = threadIdx.x;
    row[j] = input_x[b*F_ + j];
    __syncthreads();
    float s = Wb[j];
    #pragma unroll 4
    for (int c = 0; c < F_; c++) s = fmaf(row[c], Ww[c*F_ + j], s);
    g_x1[b*F_ + j] = s;
}

// ---------------- weights to bf16 ----------------
__global__ void k_cvtw(const float* __restrict__ wq, const float* __restrict__ wk,
                       const float* __restrict__ wv, const float* __restrict__ wf) {
    int i = blockIdx.x * blockDim.x + threadIdx.x;
    int e = i * 2;
    const int SQ = KQ*D_, SK = R_*KQ*D_, SF = R_*D_*D_;
    if (e < SQ) {
        *(bf162*)(g_wq16 + e) = __float22bfloat162_rn(*(const float2*)(wq + e));
    } else if (e < SQ + SK) {
        int o = e - SQ;
        *(bf162*)(g_wk16 + o) = __float22bfloat162_rn(*(const float2*)(wk + o));
    } else if (e < SQ + 2*SK) {
        int o = e - SQ - SK;
        *(bf162*)(g_wv16 + o) = __float22bfloat162_rn(*(const float2*)(wv + o));
    } else if (e < SQ + 2*SK + SF) {
        int o = e - SQ - 2*SK;
        *(bf162*)(g_wf16 + o) = __float22bfloat162_rn(*(const float2*)(wf + o));
    }
}

// inline concat loader: 8 bf16 of [node_embed | x1] row m, cols c..c+7
__device__ __forceinline__ uint4 load_cat8(const float* __restrict__ ne, int m, int c) {
    float4 f0, f1;
    if (c < D_) {
        const float* p = ne + (size_t)m*D_ + c;
        f0 = *(const float4*)p; f1 = *(const float4*)(p + 4);
    } else {
        const float* p = g_x1 + (size_t)(m >> 11)*F_ + (c - D_);
        f0 = *(const float4*)p; f1 = *(const float4*)(p + 4);
    }
    uint4 r;
    r.x = pk2(f0.x, f0.y); r.y = pk2(f0.z, f0.w);
    r.z = pk2(f1.x, f1.y); r.w = pk2(f1.z, f1.w);
    return r;
}

// ============ qkv GEMM (R7/R11-proven: CTA 128x128, 8 warps 64x32) ============
__global__ void __launch_bounds__(256) k_qkv16(
        const float* __restrict__ node_embed,
        const float* __restrict__ WQ_b, const float* __restrict__ WK_b,
        const float* __restrict__ WV_b) {
    __shared__ bf16 As[128*40];
    __shared__ bf16 Bs[32*136];
    int tid = threadIdx.x;
    int l = tid & 31, warp = tid >> 5;
    int warp_m = warp & 1, warp_n = warp >> 1;
    int quad = l >> 2, qlane = l & 3;

    int bn = blockIdx.x;
    int m0 = blockIdx.y * 128;
    int chunk = bn >> 1;
    int j0 = (bn & 1) * 128;

    const bf16* Wg; const float* bias;
    if (chunk == 0)      { Wg = g_wq16;                           bias = WQ_b; }
    else if (chunk <= 2) { Wg = g_wk16 + (size_t)(chunk-1)*KQ*D_; bias = WK_b + (chunk-1)*D_; }
    else                 { Wg = g_wv16 + (size_t)(chunk-3)*KQ*D_; bias = WV_b + (chunk-3)*D_; }

    float acc[4][4][4];
    #pragma unroll
    for (int i=0;i<4;i++) for (int j=0;j<4;j++) for (int c=0;c<4;c++) acc[i][j][c]=0.f;

    int a_row = tid >> 2, a_seg = tid & 3;
    int b_row = tid >> 4, b_seg = tid & 15;

    int arow = (l & 7) + ((l >> 3) & 1) * 8;
    int acol = (l >> 4) * 8;
    unsigned a_base = smem_u32(As) + (unsigned)(((warp_m*64 + arow)*40 + acol) * 2);
    int lt = l & 15;
    unsigned b_base = smem_u32(Bs) + (unsigned)((lt*136 + warp_n*32) * 2);

    {
        #pragma unroll
        for (int it=0; it<2; it++) {
            int r = a_row + it*64;
            *(uint4*)&As[r*40 + a_seg*8] = load_cat8(node_embed, m0 + r, a_seg*8);
            int rb = b_row + it*16;
            *(uint4*)&Bs[rb*136 + b_seg*8] =
                *(const uint4*)(Wg + (size_t)rb*D_ + j0 + b_seg*8);
        }
    }
    __syncthreads();

    for (int c0 = 0; c0 < KQ; c0 += 32) {
        bool nxt = (c0 + 32 < KQ);
        uint4 pa0,pa1,pb0,pb1;
        if (nxt) {
            pa0 = load_cat8(node_embed, m0 + a_row,      c0+32 + a_seg*8);
            pa1 = load_cat8(node_embed, m0 + a_row + 64, c0+32 + a_seg*8);
            pb0 = *(const uint4*)(Wg + (size_t)(c0+32+b_row   )*D_ + j0 + b_seg*8);
            pb1 = *(const uint4*)(Wg + (size_t)(c0+32+b_row+16)*D_ + j0 + b_seg*8);
        }
        #pragma unroll
        for (int ks = 0; ks < 2; ks++) {
            unsigned a0,a1,a2,a3;
            unsigned bfr[4][2];
            #pragma unroll
            for (int nt=0; nt<4; nt++) {
                unsigned addr = b_base + (unsigned)((ks*16*136 + nt*8) * 2);
                LDSM_X2T(bfr[nt][0], bfr[nt][1], addr);
            }
            #pragma unroll
            for (int mt=0; mt<4; mt++) {
                unsigned addr = a_base + (unsigned)((mt*16*40 + ks*16) * 2);
                LDSM_X4(a0,a1,a2,a3, addr);
                #pragma unroll
                for (int nt=0; nt<4; nt++)
                    MMA16816(acc[mt][nt], a0,a1,a2,a3, bfr[nt][0], bfr[nt][1]);
            }
        }
        __syncthreads();
        if (nxt) {
            *(uint4*)&As[(a_row   )*40 + a_seg*8] = pa0;
            *(uint4*)&As[(a_row+64)*40 + a_seg*8] = pa1;
            *(uint4*)&Bs[(b_row   )*136 + b_seg*8] = pb0;
            *(uint4*)&Bs[(b_row+16)*136 + b_seg*8] = pb1;
            __syncthreads();
        }
    }

    #pragma unroll
    for (int mt=0; mt<4; mt++) {
        #pragma unroll
        for (int half=0; half<2; half++) {
            int i = m0 + warp_m*64 + mt*16 + quad + half*8;
            int bb = i >> 11, ntok = i & (N_-1);
            #pragma unroll
            for (int nt=0; nt<4; nt++) {
                int jj = j0 + warp_n*32 + nt*8 + qlane*2;
                float2 bv = *(const float2*)(bias + jj);
                float v0 = acc[mt][nt][half*2+0] + bv.x;
                float v1 = acc[mt][nt][half*2+1] + bv.y;
                bf16* dst;
                if (chunk == 0)      dst = g_q16 + (size_t)i*D_ + jj;
                else if (chunk <= 2) dst = g_k16 + ((size_t)(bb*R_ + (chunk-1))*N_ + ntok)*D_ + jj;
                else                 dst = g_v16 + ((size_t)(bb*R_ + (chunk-3))*N_ + ntok)*D_ + jj;
                *(bf162*)dst = __float22bfloat162_rn(make_float2(v0, v1));
            }
        }
    }
}

// ============ fused attention (R11-proven): 64 q-rows/CTA, 256 thr, 2 CTAs/SM ======
// 8 warps: wm = warp&3 (16 q-rows), wd = warp>>2.
// S phase:  warp tile m16 x kv32 (wd = kv-half of 32), k=256
// PV phase: warp tile m16 x d128 (wd = d-half of 128), k=64
// smem: q[64][264] | K[64][264] | V[64][264] | P[64][72] | rs[2][64]
// cp.async rotating schedule: K(t+1) issued post-S barrier (overlaps PV(t)),
// V(t+1) issued post-PV barrier (overlaps S(t+1)).
#define AT_Q   0
#define AT_K   33792
#define AT_V   67584
#define AT_P   101376
#define AT_RS  110592
#define AT_TOT 111104
#define NT64   (N_/64)

__global__ void __launch_bounds__(256, 2) k_attn(const int* __restrict__ adj) {
    extern __shared__ char dsm[];
    unsigned sbase = smem_u32(dsm);
    int tid = threadIdx.x;
    int l = tid & 31, warp = tid >> 5;   // 8 warps
    int wm = warp & 3, wd = warp >> 2;
    int quad = l >> 2, qlane = l & 3;

    int m0 = blockIdx.x * 64;
    int p  = blockIdx.y;

    const bf16* gq = g_q16 + ((size_t)(p >> 1)*N_ + m0)*D_;
    const bf16* gk = g_k16 + (size_t)p*N_*D_;
    const bf16* gv = g_v16 + (size_t)p*N_*D_;
    const int2* adj0 = (const int2*)(adj + ((size_t)p*N_ + m0 + wm*16 + quad    )*N_ + wd*32) + qlane;
    const int2* adj8 = (const int2*)(adj + ((size_t)p*N_ + m0 + wm*16 + quad + 8)*N_ + wd*32) + qlane;

    #pragma unroll
    for (int it = 0; it < 8; it++) {
        int c = it*256 + tid;
        int row = c >> 5, seg = c & 31;
        CPA16(sbase + AT_Q + (unsigned)(row*528 + seg*16), gq + (size_t)row*D_ + seg*8);
    }
    #pragma unroll
    for (int it = 0; it < 8; it++) {
        int c = it*256 + tid;
        int row = c >> 5, seg = c & 31;
        CPA16(sbase + AT_K + (unsigned)(row*528 + seg*16), gk + (size_t)row*D_ + seg*8);
    }
    CPA_COMMIT();
    #pragma unroll
    for (int it = 0; it < 8; it++) {
        int c = it*256 + tid;
        int row = c >> 5, seg = c & 31;
        CPA16(sbase + AT_V + (unsigned)(row*528 + seg*16), gv + (size_t)row*D_ + seg*8);
    }
    CPA_COMMIT();

    float o[16][4];
    #pragma unroll
    for (int i=0;i<16;i++) { o[i][0]=0.f;o[i][1]=0.f;o[i][2]=0.f;o[i][3]=0.f; }
    float rs0 = 0.f, rs1 = 0.f;

    unsigned qa = sbase + AT_Q +
        (unsigned)(((wm*16 + (l & 7) + ((l >> 3) & 1)*8)*264 + (l >> 4)*8) * 2);
    unsigned kbb = sbase + AT_K +
        (unsigned)(((wd*32 + (l & 7) + ((l >> 4) & 1)*8)*264 + ((l >> 3) & 1)*8) * 2);
    unsigned pa = sbase + AT_P +
        (unsigned)(((wm*16 + (l & 7) + ((l >> 3) & 1)*8)*72 + (l >> 4)*8) * 2);
    unsigned vbb = sbase + AT_V +
        (unsigned)(((l & 15)*264 + wd*128 + ((l >> 4) & 1)*8) * 2);

    bf16* Psm = (bf16*)(dsm + AT_P);
    float* rsm = (float*)(dsm + AT_RS);

    for (int t = 0; t < NT64; t++) {
        CPA_WAIT1();
        __syncthreads();

        int2 am[8];
        #pragma unroll
        for (int nt = 0; nt < 4; nt++) {
            am[nt]     = adj0[t*32 + nt*4];
            am[4 + nt] = adj8[t*32 + nt*4];
        }

        float sc[4][4];
        #pragma unroll
        for (int i=0;i<4;i++){sc[i][0]=0.f;sc[i][1]=0.f;sc[i][2]=0.f;sc[i][3]=0.f;}
        #pragma unroll
        for (int ks = 0; ks < 16; ks++) {
            unsigned a0,a1,a2,a3;
            LDSM_X4(a0,a1,a2,a3, qa + (unsigned)(ks*32));
            #pragma unroll
            for (int nt16 = 0; nt16 < 2; nt16++) {
                unsigned b0,b1,b2,b3;
                LDSM_X4(b0,b1,b2,b3, kbb + (unsigned)((nt16*16*264 + ks*16) * 2));
                MMA16816(sc[nt16*2  ], a0,a1,a2,a3, b0,b1);
                MMA16816(sc[nt16*2+1], a0,a1,a2,a3, b2,b3);
            }
        }

        {
            int r0 = wm*16 + quad;
            #pragma unroll
            for (int nt = 0; nt < 4; nt++) {
                float e00 = am[nt].x   ? __expf(sc[nt][0]*0.0625f) : 0.f;
                float e01 = am[nt].y   ? __expf(sc[nt][1]*0.0625f) : 0.f;
                float e10 = am[4+nt].x ? __expf(sc[nt][2]*0.0625f) : 0.f;
                float e11 = am[4+nt].y ? __expf(sc[nt][3]*0.0625f) : 0.f;
                rs0 += e00 + e01;
                rs1 += e10 + e11;
                int col = wd*32 + nt*8 + qlane*2;
                *(unsigned*)(Psm + r0*72 + col)     = pk2(e00, e01);
                *(unsigned*)(Psm + (r0+8)*72 + col) = pk2(e10, e11);
            }
        }
        __syncthreads();   // P ready; K buffer free

        if (t + 1 < NT64) {
            const bf16* gk1 = gk + (size_t)(t+1)*64*D_;
            #pragma unroll
            for (int it = 0; it < 8; it++) {
                int c = it*256 + tid;
                int row = c >> 5, seg = c & 31;
                CPA16(sbase + AT_K + (unsigned)(row*528 + seg*16),
                      gk1 + (size_t)row*D_ + seg*8);
            }
        }
        CPA_COMMIT();

        CPA_WAIT1();
        __syncthreads();

        #pragma unroll
        for (int ks2 = 0; ks2 < 4; ks2++) {
            unsigned a0,a1,a2,a3;
            LDSM_X4(a0,a1,a2,a3, pa + (unsigned)(ks2*32));
            #pragma unroll
            for (int nt16 = 0; nt16 < 8; nt16++) {
                unsigned b0,b1,b2,b3;
                LDSM_X4T(b0,b1,b2,b3, vbb + (unsigned)((ks2*16*264 + nt16*16) * 2));
                MMA16816(o[nt16*2  ], a0,a1,a2,a3, b0,b1);
                MMA16816(o[nt16*2+1], a0,a1,a2,a3, b2,b3);
            }
        }
        __syncthreads();   // V buffer free

        if (t + 1 < NT64) {
            const bf16* gv1 = gv + (size_t)(t+1)*64*D_;
            #pragma unroll
            for (int it = 0; it < 8; it++) {
                int c = it*256 + tid;
                int row = c >> 5, seg = c & 31;
                CPA16(sbase + AT_V + (unsigned)(row*528 + seg*16),
                      gv1 + (size_t)row*D_ + seg*8);
            }
        }
        CPA_COMMIT();
    }

    rs0 += __shfl_xor_sync(0xffffffffu, rs0, 1);
    rs0 += __shfl_xor_sync(0xffffffffu, rs0, 2);
    rs1 += __shfl_xor_sync(0xffffffffu, rs1, 1);
    rs1 += __shfl_xor_sync(0xffffffffu, rs1, 2);
    if (qlane == 0) {
        rsm[wd*64 + wm*16 + quad]     = rs0;
        rsm[wd*64 + wm*16 + quad + 8] = rs1;
    }
    __syncthreads();

    {
        int r = wm*16 + quad;
        float ta = rsm[r]     + rsm[64 + r];
        float tb = rsm[r + 8] + rsm[64 + r + 8];
        float ia = ta > 0.f ? __fdividef(1.f, ta) : 0.f;
        float ib = tb > 0.f ? __fdividef(1.f, tb) : 0.f;
        bf16* d0 = g_h16 + ((size_t)((p >> 1)*N_ + m0 + r))*(R_*D_) + (p & 1)*D_ + wd*128;
        bf16* d1 = d0 + (size_t)8*(R_*D_);
        #pragma unroll
        for (int nt = 0; nt < 16; nt++) {
            int col = nt*8 + qlane*2;
            *(unsigned*)(d0 + col) = pk2(o[nt][0]*ia, o[nt][1]*ia);
            *(unsigned*)(d1 + col) = pk2(o[nt][2]*ib, o[nt][3]*ib);
        }
    }
}

// ============ h_fused GEMM + relu + residual + LN (mma.sync, proven) ============
__global__ void __launch_bounds__(256) k_fused16(
        const float* __restrict__ node_embed,
        const float* __restrict__ WF_b,
        const float* __restrict__ ln_g, const float* __restrict__ ln_b,
        float* __restrict__ out) {
    __shared__ bf16 As[64*40];
    __shared__ bf16 Bs[32*264];
    __shared__ float2 part[64][4];
    int tid = threadIdx.x;
    int l = tid & 31, warp = tid >> 5;
    int warp_m = warp & 1, warp_n = warp >> 1;
    int quad = l >> 2, qlane = l & 3;
    int m0 = blockIdx.x * 64;

    float acc[2][8][4];
    #pragma unroll
    for (int i=0;i<2;i++) for (int j=0;j<8;j++) for (int c=0;c<4;c++) acc[i][j][c]=0.f;

    int a_row = tid >> 2, a_seg = tid & 3;
    int b_row = tid >> 5, b_seg = tid & 31;

    int arow = (l & 7) + ((l >> 3) & 1) * 8;
    int acol = (l >> 4) * 8;
    unsigned a_base = smem_u32(As) + (unsigned)(((warp_m*32 + arow)*40 + acol) * 2);
    int lt = l & 15;
    unsigned b_base = smem_u32(Bs) + (unsigned)((lt*264 + warp_n*64) * 2);

    {
        *(uint4*)&As[a_row*40 + a_seg*8] =
            *(const uint4*)(g_h16 + (size_t)(m0+a_row)*(R_*D_) + a_seg*8);
        #pragma unroll
        for (int it=0; it<4; it++) {
            int rb = b_row + it*8;
            *(uint4*)&Bs[rb*264 + b_seg*8] =
                *(const uint4*)(g_wf16 + (size_t)rb*D_ + b_seg*8);
        }
    }
    __syncthreads();

    for (int c0 = 0; c0 < R_*D_; c0 += 32) {
        bool nxt = (c0 + 32 < R_*D_);
        uint4 pa0, pb[4];
        if (nxt) {
            pa0 = *(const uint4*)(g_h16 + (size_t)(m0+a_row)*(R_*D_) + c0+32 + a_seg*8);
            #pragma unroll
            for (int it=0; it<4; it++)
                pb[it] = *(const uint4*)(g_wf16 + (size_t)(c0+32+b_row+it*8)*D_ + b_seg*8);
        }
        #pragma unroll
        for (int ks = 0; ks < 2; ks++) {
            unsigned a0,a1,a2,a3;
            unsigned bfr[8][2];
            #pragma unroll
            for (int nt=0; nt<8; nt++) {
                unsigned addr = b_base + (unsigned)((ks*16*264 + nt*8) * 2);
                LDSM_X2T(bfr[nt][0], bfr[nt][1], addr);
            }
            #pragma unroll
            for (int mt=0; mt<2; mt++) {
                unsigned addr = a_base + (unsigned)((mt*16*40 + ks*16) * 2);
                LDSM_X4(a0,a1,a2,a3, addr);
                #pragma unroll
                for (int nt=0; nt<8; nt++)
                    MMA16816(acc[mt][nt], a0,a1,a2,a3, bfr[nt][0], bfr[nt][1]);
            }
        }
        __syncthreads();
        if (nxt) {
            *(uint4*)&As[a_row*40 + a_seg*8] = pa0;
            #pragma unroll
            for (int it=0; it<4; it++)
                *(uint4*)&Bs[(b_row+it*8)*264 + b_seg*8] = pb[it];
            __syncthreads();
        }
    }

    #pragma unroll
    for (int mt=0; mt<2; mt++) {
        #pragma unroll
        for (int half=0; half<2; half++) {
            int row_l = warp_m*32 + mt*16 + quad + half*8;
            int grow = m0 + row_l;
            float s = 0.f, sq = 0.f;
            #pragma unroll
            for (int nt=0; nt<8; nt++) {
                int col = warp_n*64 + nt*8 + qlane*2;
                float2 bb = *(const float2*)(WF_b + col);
                float h0 = acc[mt][nt][half*2+0] + bb.x; h0 = h0 > 0.f ? h0 : 0.f;
                float h1 = acc[mt][nt][half*2+1] + bb.y; h1 = h1 > 0.f ? h1 : 0.f;
                float2 ne = *(const float2*)(node_embed + (size_t)grow*D_ + col);
                float y0 = ne.x + h0, y1 = ne.y + h1;
                acc[mt][nt][half*2+0] = y0;
                acc[mt][nt][half*2+1] = y1;
                s += y0 + y1;
                sq = fmaf(y0, y0, fmaf(y1, y1, sq));
            }
            s  += __shfl_xor_sync(0xffffffffu, s, 1);
            s  += __shfl_xor_sync(0xffffffffu, s, 2);
            sq += __shfl_xor_sync(0xffffffffu, sq, 1);
            sq += __shfl_xor_sync(0xffffffffu, sq, 2);
            if (qlane == 0) part[row_l][warp_n] = make_float2(s, sq);
        }
    }
    __syncthreads();
    #pragma unroll
    for (int mt=0; mt<2; mt++) {
        #pragma unroll
        for (int half=0; half<2; half++) {
            int row_l = warp_m*32 + mt*16 + quad + half*8;
            int grow = m0 + row_l;
            float s = 0.f, sq = 0.f;
            #pragma unroll
            for (int w=0; w<4; w++) { float2 pp = part[row_l][w]; s += pp.x; sq += pp.y; }
            float mu = s * (1.0f/256.0f);
            float var = sq * (1.0f/256.0f) - mu*mu;
            float rstd = rsqrtf(var + 1e-5f);
            #pragma unroll
            for (int nt=0; nt<8; nt++) {
                int col = warp_n*64 + nt*8 + qlane*2;
                float2 gg = *(const float2*)(ln_g + col);
                float2 bb = *(const float2*)(ln_b + col);
                float y0 = acc[mt][nt][half*2+0];
                float y1 = acc[mt][nt][half*2+1];
                float2 o;
                o.x = (y0 - mu) * rstd * gg.x + bb.x;
                o.y = (y1 - mu) * rstd * gg.y + bb.y;
                *(float2*)(out + (size_t)grow*D_ + col) = o;
            }
        }
    }
}

// ---------------- launch ----------------
extern "C" void kernel_launch(void* const* d_in, const int* in_sizes, int n_in,
                              void* d_out, int out_size) {
    const float* node_embed = (const float*)d_in[0];
    const float* input_x    = (const float*)d_in[1];
    const int*   adj        = (const int*)  d_in[2];
    const float* WQi_w      = (const float*)d_in[3];
    const float* WQi_b      = (const float*)d_in[4];
    const float* WQ_w       = (const float*)d_in[5];
    const float* WQ_b       = (const float*)d_in[6];
    const float* WK_w       = (const float*)d_in[7];
    const float* WK_b       = (const float*)d_in[8];
    const float* WV_w       = (const float*)d_in[9];
    const float* WV_b       = (const float*)d_in[10];
    const float* WF_w       = (const float*)d_in[11];
    const float* WF_b       = (const float*)d_in[12];
    const float* ln_g       = (const float*)d_in[13];
    const float* ln_b       = (const float*)d_in[14];
    float* out = (float*)d_out;

    cudaFuncSetAttribute(k_attn, cudaFuncAttributeMaxDynamicSharedMemorySize, AT_TOT);

    k_x1      <<<B_, F_>>>(input_x, WQi_w, WQi_b);
    k_cvtw    <<<1216, 256>>>(WQ_w, WK_w, WV_w, WF_w);
    k_qkv16   <<<dim3(10, 128), 256>>>(node_embed, WQ_b, WK_b, WV_b);
    k_attn    <<<dim3(32, B_*R_), 256, AT_TOT>>>(adj);
    k_fused16 <<<M_TOT/64, 256>>>(node_embed, WF_b, ln_g, ln_b, out);
}